// round 4
// baseline (speedup 1.0000x reference)
#include <cuda_runtime.h>
#include <cuda_bf16.h>
#include <math.h>

// Problem dims
#define Bn 512
#define Tn 512
#define In 256
#define Hn 250

// ---------------- packed f32x2 helpers (sm_100+) -----------------------------
__device__ __forceinline__ unsigned long long pack2(float a, float b) {
    unsigned long long r;
    asm("mov.b64 %0, {%1, %2};" : "=l"(r) : "f"(a), "f"(b));
    return r;
}
__device__ __forceinline__ void fma2(unsigned long long& d,
                                     unsigned long long a,
                                     unsigned long long b) {
    asm("fma.rn.f32x2 %0, %1, %2, %0;" : "+l"(d) : "l"(a), "l"(b));
}
__device__ __forceinline__ void unpack2(unsigned long long v, float& lo, float& hi) {
    asm("mov.b64 {%0, %1}, %2;" : "=f"(lo), "=f"(hi) : "l"(v));
}

// ---------------- Phase 1: xproj GEMM  out[m, j] = sum_i x[m,i] * Wx[j,i] ----
// M = B*T = 262144, K = 256, N = 250. Written in-place into d_out [B,T,H].
#define BM 128
#define BN 128
#define BK 16
#define TM 8
#define GEMM_THREADS 256
#define SPAD 132   // smem row stride (padded, 528B = multiple of 16)

__global__ __launch_bounds__(GEMM_THREADS)
void gemm_xproj_kernel(const float* __restrict__ X,
                       const float* __restrict__ Wx,
                       float* __restrict__ out) {
    __shared__ float As[BK][SPAD];
    __shared__ float Bs[BK][SPAD];

    const int t  = threadIdx.x;
    const int m0 = blockIdx.x * BM;
    const int j0 = blockIdx.y * BN;

    const int tx = t & 15;   // 0..15 -> N direction (8 cols each)
    const int ty = t >> 4;   // 0..15 -> M direction (8 rows each)

    const int lr = t >> 2;   // 0..63 load row
    const int lc = t & 3;    // 0..3  float4 col within 16-wide k tile

    // packed accumulators: acc2[i][p] = (C[i][2p], C[i][2p+1])
    unsigned long long acc2[TM][4];
    #pragma unroll
    for (int i = 0; i < TM; i++)
        #pragma unroll
        for (int p = 0; p < 4; p++)
            acc2[i][p] = 0ULL;

    for (int k0 = 0; k0 < In; k0 += BK) {
        // load A tile (128 rows x 16 k), store transposed As[k][m]
        #pragma unroll
        for (int rr = 0; rr < 2; rr++) {
            int m = lr + rr * 64;
            float4 v = *(const float4*)(X + (size_t)(m0 + m) * In + k0 + lc * 4);
            As[lc * 4 + 0][m] = v.x;
            As[lc * 4 + 1][m] = v.y;
            As[lc * 4 + 2][m] = v.z;
            As[lc * 4 + 3][m] = v.w;
        }
        // load B tile: Bs[k][j] = Wx[j0+j][k0+k], zero-fill j >= 250
        #pragma unroll
        for (int rr = 0; rr < 2; rr++) {
            int jj = lr + rr * 64;
            int gj = j0 + jj;
            float4 v = make_float4(0.f, 0.f, 0.f, 0.f);
            if (gj < Hn)
                v = *(const float4*)(Wx + (size_t)gj * In + k0 + lc * 4);
            Bs[lc * 4 + 0][jj] = v.x;
            Bs[lc * 4 + 1][jj] = v.y;
            Bs[lc * 4 + 2][jj] = v.z;
            Bs[lc * 4 + 3][jj] = v.w;
        }
        __syncthreads();

        #pragma unroll
        for (int kk = 0; kk < BK; kk++) {
            // b pairs come pre-packed from smem (consecutive floats)
            ulonglong2 bA = *(const ulonglong2*)(&Bs[kk][tx * TM]);      // b01,b23
            ulonglong2 bB = *(const ulonglong2*)(&Bs[kk][tx * TM + 4]);  // b45,b67
            float4 a0 = *(const float4*)(&As[kk][ty * TM + 0]);
            float4 a1 = *(const float4*)(&As[kk][ty * TM + 4]);
            float a[TM] = {a0.x, a0.y, a0.z, a0.w, a1.x, a1.y, a1.z, a1.w};
            #pragma unroll
            for (int i = 0; i < TM; i++) {
                unsigned long long aa = pack2(a[i], a[i]);   // broadcast pack
                fma2(acc2[i][0], aa, bA.x);
                fma2(acc2[i][1], aa, bA.y);
                fma2(acc2[i][2], aa, bB.x);
                fma2(acc2[i][3], aa, bB.y);
            }
        }
        __syncthreads();
    }

    // epilogue: out row stride = 250
    #pragma unroll
    for (int i = 0; i < TM; i++) {
        int m = m0 + ty * TM + i;
        float c[8];
        #pragma unroll
        for (int p = 0; p < 4; p++)
            unpack2(acc2[i][p], c[2 * p], c[2 * p + 1]);
        #pragma unroll
        for (int jj = 0; jj < 8; jj++) {
            int gj = j0 + tx * TM + jj;
            if (gj < Hn)
                out[(size_t)m * Hn + gj] = c[jj];
        }
    }
}

// ---------------- Phase 2: recurrent scan -----------------------------------
// 128 CTAs x 4 batches. Thread j computes h_new[bb][j] = tanh(xp + Wh[j,:].h + b).
// Wh row split: cols 0..127 cached in smem (stride 132, conflict-free LDS.128),
// cols 128..255 (zero-padded past 249) held in 64 packed-pair registers for the
// whole t-loop. h ping-pongs in smem (broadcast reads). All math via f32x2.
#define KC   128                    // k columns cached in smem
#define KC2  (KC / 4)               // 32 ulonglong2 chunks in smem part
#define WQ   32                     // 32 register chunks (k = 128..255)
#define WSTR 132                    // smem Wh row stride
#define HBUF 256                    // padded h row (cols 250..255 stay 0)
#define SCAN_SMEM_BYTES (Hn * WSTR * 4 + 2 * 4 * HBUF * 4)

__global__ __launch_bounds__(256, 1)
void rnn_scan_kernel(const float* __restrict__ h0,
                     const float* __restrict__ Wh,
                     const float* __restrict__ bh,
                     float* out) {
    extern __shared__ float sm[];
    float* WhS = sm;                    // [250][132] (cols 0..127 valid)
    float* hb  = sm + Hn * WSTR;        // [2][4][256]

    const int j  = threadIdx.x;                 // 0..255
    const int jj = (j < Hn) ? j : (Hn - 1);     // clamp for lanes 250..255
    const int b0 = blockIdx.x * 4;

    // fill smem Wh cache: cols 0..127 of every row
    for (int idx = j; idx < Hn * KC; idx += 256) {
        int r = idx >> 7;          // / 128
        int c = idx & 127;
        WhS[r * WSTR + c] = Wh[r * Hn + c];
    }
    // zero both h buffers (keeps pad cols 250..255 at 0 forever)
    for (int idx = j; idx < 2 * 4 * HBUF; idx += 256)
        hb[idx] = 0.0f;
    __syncthreads();
    // load initial h into buffer 0
    if (j < Hn) {
        #pragma unroll
        for (int bb = 0; bb < 4; bb++)
            hb[bb * HBUF + j] = h0[(size_t)(b0 + bb) * Hn + j];
    }

    const float bias = bh[jj];

    // register-resident tail of Wh row jj: k = 128..255, packed pairs,
    // zero-filled for k >= 250 (Wh rows are 250 floats, not 16B aligned ->
    // scalar bounds-checked loads, one-time cost).
    unsigned long long wlo[WQ], whi[WQ];
    {
        const float* row = Wh + (size_t)jj * Hn;
        #pragma unroll
        for (int q = 0; q < WQ; q++) {
            int k = KC + 4 * q;
            float f0 = (k + 0 < Hn) ? row[k + 0] : 0.0f;
            float f1 = (k + 1 < Hn) ? row[k + 1] : 0.0f;
            float f2 = (k + 2 < Hn) ? row[k + 2] : 0.0f;
            float f3 = (k + 3 < Hn) ? row[k + 3] : 0.0f;
            wlo[q] = pack2(f0, f1);
            whi[q] = pack2(f2, f3);
        }
    }
    __syncthreads();

    int p = 0;
    for (int t = 0; t < Tn; t++) {
        // prefetch xproj for this step (consumed after the k-loop)
        float xp[4];
        if (j < Hn) {
            #pragma unroll
            for (int bb = 0; bb < 4; bb++)
                xp[bb] = out[((size_t)(b0 + bb) * Tn + t) * Hn + j];
        } else {
            xp[0] = xp[1] = xp[2] = xp[3] = 0.0f;
        }

        unsigned long long acc2[4];
        #pragma unroll
        for (int bb = 0; bb < 4; bb++) acc2[bb] = 0ULL;

        // packed-pair view of h buffer: [4][64] ulonglong2 chunks
        const ulonglong2* hb2 = (const ulonglong2*)(hb + p * (4 * HBUF));

        // smem part: k = 0..127
        const ulonglong2* wrow2 = (const ulonglong2*)(WhS + jj * WSTR);
        #pragma unroll 8
        for (int kc = 0; kc < KC2; kc++) {
            ulonglong2 w = wrow2[kc];
            #pragma unroll
            for (int bb = 0; bb < 4; bb++) {
                ulonglong2 hv = hb2[bb * 64 + kc];    // warp-uniform broadcast
                fma2(acc2[bb], w.x, hv.x);
                fma2(acc2[bb], w.y, hv.y);
            }
        }
        // register part: k = 128..255 (pad contributes 0)
        #pragma unroll 8
        for (int q = 0; q < WQ; q++) {
            #pragma unroll
            for (int bb = 0; bb < 4; bb++) {
                ulonglong2 hv = hb2[bb * 64 + KC2 + q];
                fma2(acc2[bb], wlo[q], hv.x);
                fma2(acc2[bb], whi[q], hv.y);
            }
        }

        float* hnx = hb + (1 - p) * (4 * HBUF);
        #pragma unroll
        for (int bb = 0; bb < 4; bb++) {
            float lo, hi;
            unpack2(acc2[bb], lo, hi);
            float hv = tanhf(lo + hi + bias + xp[bb]);
            if (j < Hn) {
                hnx[bb * HBUF + j] = hv;
                out[((size_t)(b0 + bb) * Tn + t) * Hn + j] = hv;
            }
        }
        __syncthreads();
        p ^= 1;
    }
}

// ---------------- launch ------------------------------------------------------
extern "C" void kernel_launch(void* const* d_in, const int* in_sizes, int n_in,
                              void* d_out, int out_size) {
    const float* x  = (const float*)d_in[0];   // [512,512,256]
    const float* h0 = (const float*)d_in[1];   // [512,250]
    const float* Wx = (const float*)d_in[2];   // [250,256]
    const float* Wh = (const float*)d_in[3];   // [250,250]
    const float* bh = (const float*)d_in[4];   // [250]
    float* out = (float*)d_out;                // [512,512,250]

    // 1) xproj GEMM straight into d_out
    dim3 grid((Bn * Tn) / BM, 2);
    gemm_xproj_kernel<<<grid, GEMM_THREADS>>>(x, Wx, out);

    // 2) recurrent scan (in-place over d_out)
    cudaFuncSetAttribute(rnn_scan_kernel,
                         cudaFuncAttributeMaxDynamicSharedMemorySize,
                         SCAN_SMEM_BYTES);
    rnn_scan_kernel<<<(Bn / 4), 256, SCAN_SMEM_BYTES>>>(h0, Wh, bh, out);
}

// round 7
// speedup vs baseline: 1.2862x; 1.2862x over previous
#include <cuda_runtime.h>
#include <cuda_bf16.h>
#include <math.h>
#include <stdint.h>

// Problem dims
#define Bn 512
#define Tn 512
#define In 256
#define Hn 250

// ---------------- helpers ----------------------------------------------------
__device__ __forceinline__ uint32_t smem_u32(const void* p) {
    uint32_t a;
    asm("{ .reg .u64 t; cvta.to.shared.u64 t, %1; cvt.u32.u64 %0, t; }"
        : "=r"(a) : "l"(p));
    return a;
}
// pack (lo, hi) floats into bf16x2 word (lo in low half)
__device__ __forceinline__ uint32_t bf16x2_rn(float lo, float hi) {
    uint32_t r;
    asm("cvt.rn.bf16x2.f32 %0, %1, %2;" : "=r"(r) : "f"(hi), "f"(lo));
    return r;
}
__device__ __forceinline__ void ldsm4(uint32_t* r, uint32_t addr) {
    asm volatile("ldmatrix.sync.aligned.m8n8.x4.shared.b16 {%0,%1,%2,%3}, [%4];"
                 : "=r"(r[0]), "=r"(r[1]), "=r"(r[2]), "=r"(r[3]) : "r"(addr));
}
__device__ __forceinline__ void mma16816(float* c, const uint32_t* a,
                                         const uint32_t* b) {
    asm volatile(
        "mma.sync.aligned.m16n8k16.row.col.f32.bf16.bf16.f32 "
        "{%0,%1,%2,%3}, {%4,%5,%6,%7}, {%8,%9}, {%0,%1,%2,%3};"
        : "+f"(c[0]), "+f"(c[1]), "+f"(c[2]), "+f"(c[3])
        : "r"(a[0]), "r"(a[1]), "r"(a[2]), "r"(a[3]), "r"(b[0]), "r"(b[1]));
}

// ---------------- scratch ----------------------------------------------------
__device__ float g_WhP[Hn * 256];          // Wh padded [250][256]
__device__ uint4 g_WxH4[256 * 32];         // Wx hi bf16 [256 n][256 k]
__device__ uint4 g_WxL4[256 * 32];         // Wx lo bf16 [256 n][256 k]

__global__ void prep_whp_kernel(const float* __restrict__ Wh) {
    int i = blockIdx.x * blockDim.x + threadIdx.x;   // 250*256 threads
    int r = i >> 8;
    int k = i & 255;
    g_WhP[i] = (k < Hn) ? Wh[r * Hn + k] : 0.0f;
}

__global__ void prep_wx_kernel(const float* __restrict__ Wx) {
    int i = blockIdx.x * blockDim.x + threadIdx.x;   // 256*256 threads
    int r = i >> 8;
    int k = i & 255;
    float w = (r < Hn) ? Wx[r * In + k] : 0.0f;
    // truncation split: hi = upper 16 bits, lo = rounded remainder
    uint32_t wb = __float_as_uint(w);
    float hif = __uint_as_float(wb & 0xFFFF0000u);
    float rem = w - hif;
    ((unsigned short*)g_WxH4)[i] = (unsigned short)(wb >> 16);
    __nv_bfloat16 lo = __float2bfloat16(rem);
    ((unsigned short*)g_WxL4)[i] = __bfloat16_as_ushort(lo);
}

// ---------------- Phase 1: xproj via HMMA bf16-split GEMM --------------------
// out[m, j] = sum_k x[m,k] * Wx[j,k];  M = 262144, N = 256 (250 valid), K = 256.
// CTA tile 128x128x32, warp tile 32x64, 3 bf16 products accumulated in fp32.
#define SBH 80            // smem row stride in bytes (40 bf16)
#define ABUF (128 * SBH)  // 10240 B per buffer

__global__ __launch_bounds__(256, 1)
void gemm_xproj_hmma(const float* __restrict__ X, float* __restrict__ out) {
    __shared__ __align__(16) char smc[4 * ABUF];   // Ah, Al, Bh, Bl
    const uint32_t smb = smem_u32(smc);
    const uint32_t sAh = smb, sAl = smb + ABUF, sBh = smb + 2 * ABUF,
                   sBl = smb + 3 * ABUF;

    const int tid  = threadIdx.x;
    const int lane = tid & 31;
    const int warp = tid >> 5;
    const int wm = warp >> 1;          // 0..3 -> M offset 32*wm
    const int wn = warp & 1;           // 0..1 -> N offset 64*wn
    const size_t m0 = (size_t)blockIdx.x * 128;
    const int n0c = blockIdx.y * 128;

    // per-thread load geometry
    const int am = tid >> 1;           // A row 0..127
    const int ah = tid & 1;            // A k-half (16 floats)
    const float* aptr = X + (m0 + am) * In + ah * 16;
    const int nb0 = tid >> 2,  kb0 = tid & 3;            // B uint4 slot 0
    const int nb1 = (tid + 256) >> 2, kb1 = (tid + 256) & 3;  // slot 1

    float acc[2][8][4];
    #pragma unroll
    for (int mi = 0; mi < 2; mi++)
        #pragma unroll
        for (int ni = 0; ni < 8; ni++)
            #pragma unroll
            for (int q = 0; q < 4; q++) acc[mi][ni][q] = 0.0f;

    // ldmatrix base addresses (bytes)
    const uint32_t aoffm = (uint32_t)((wm * 32 + (lane & 15)) * SBH + (lane >> 4) * 16);
    const uint32_t a_h = sAh + aoffm, a_l = sAl + aoffm;
    const uint32_t boffn = (uint32_t)((wn * 64 + (lane >> 4) * 8 + (lane & 7)) * SBH +
                                      ((lane >> 3) & 1) * 16);
    const uint32_t b_h = sBh + boffn, b_l = sBl + boffn;

    // prefetch chunk 0
    float4 va[4];
    uint4 vbh[2], vbl[2];
    #pragma unroll
    for (int q = 0; q < 4; q++) va[q] = *(const float4*)(aptr + q * 4);
    vbh[0] = g_WxH4[(n0c + nb0) * 32 + kb0];
    vbh[1] = g_WxH4[(n0c + nb1) * 32 + kb1];
    vbl[0] = g_WxL4[(n0c + nb0) * 32 + kb0];
    vbl[1] = g_WxL4[(n0c + nb1) * 32 + kb1];

    for (int c = 0; c < 8; c++) {
        // ---- store staged regs to smem (A: fp32 -> bf16 hi/lo split) ----
        {
            uint4 h0, h1, l0, l1;
            h0.x = __byte_perm(__float_as_uint(va[0].x), __float_as_uint(va[0].y), 0x7632);
            h0.y = __byte_perm(__float_as_uint(va[0].z), __float_as_uint(va[0].w), 0x7632);
            h0.z = __byte_perm(__float_as_uint(va[1].x), __float_as_uint(va[1].y), 0x7632);
            h0.w = __byte_perm(__float_as_uint(va[1].z), __float_as_uint(va[1].w), 0x7632);
            h1.x = __byte_perm(__float_as_uint(va[2].x), __float_as_uint(va[2].y), 0x7632);
            h1.y = __byte_perm(__float_as_uint(va[2].z), __float_as_uint(va[2].w), 0x7632);
            h1.z = __byte_perm(__float_as_uint(va[3].x), __float_as_uint(va[3].y), 0x7632);
            h1.w = __byte_perm(__float_as_uint(va[3].z), __float_as_uint(va[3].w), 0x7632);
            #define REM(f) ((f) - __uint_as_float(__float_as_uint(f) & 0xFFFF0000u))
            l0.x = bf16x2_rn(REM(va[0].x), REM(va[0].y));
            l0.y = bf16x2_rn(REM(va[0].z), REM(va[0].w));
            l0.z = bf16x2_rn(REM(va[1].x), REM(va[1].y));
            l0.w = bf16x2_rn(REM(va[1].z), REM(va[1].w));
            l1.x = bf16x2_rn(REM(va[2].x), REM(va[2].y));
            l1.y = bf16x2_rn(REM(va[2].z), REM(va[2].w));
            l1.z = bf16x2_rn(REM(va[3].x), REM(va[3].y));
            l1.w = bf16x2_rn(REM(va[3].z), REM(va[3].w));
            #undef REM
            char* pa = smc + am * SBH + ah * 32;
            *(uint4*)(pa)              = h0;
            *(uint4*)(pa + 16)         = h1;
            *(uint4*)(pa + ABUF)       = l0;
            *(uint4*)(pa + ABUF + 16)  = l1;
            char* pb0 = smc + 2 * ABUF + nb0 * SBH + kb0 * 16;
            char* pb1 = smc + 2 * ABUF + nb1 * SBH + kb1 * 16;
            *(uint4*)(pb0)        = vbh[0];
            *(uint4*)(pb1)        = vbh[1];
            *(uint4*)(pb0 + ABUF) = vbl[0];
            *(uint4*)(pb1 + ABUF) = vbl[1];
        }
        __syncthreads();

        // ---- prefetch next chunk (overlaps with mma below) ----
        if (c < 7) {
            #pragma unroll
            for (int q = 0; q < 4; q++)
                va[q] = *(const float4*)(aptr + (c + 1) * 32 + q * 4);
            vbh[0] = g_WxH4[(n0c + nb0) * 32 + (c + 1) * 4 + kb0];
            vbh[1] = g_WxH4[(n0c + nb1) * 32 + (c + 1) * 4 + kb1];
            vbl[0] = g_WxL4[(n0c + nb0) * 32 + (c + 1) * 4 + kb0];
            vbl[1] = g_WxL4[(n0c + nb1) * 32 + (c + 1) * 4 + kb1];
        }

        // ---- compute: 2 k16 steps x 3 products ----
        #pragma unroll
        for (int ks = 0; ks < 2; ks++) {
            const uint32_t ko = ks * 32;
            uint32_t ahf[2][4], alf[2][4], bf[8][2];
            ldsm4(ahf[0], a_h + ko);
            ldsm4(ahf[1], a_h + 16 * SBH + ko);
            ldsm4(alf[0], a_l + ko);
            ldsm4(alf[1], a_l + 16 * SBH + ko);
            #pragma unroll
            for (int jp = 0; jp < 4; jp++) {
                uint32_t r[4];
                ldsm4(r, b_h + jp * 16 * SBH + ko);
                bf[jp * 2][0] = r[0]; bf[jp * 2][1] = r[1];
                bf[jp * 2 + 1][0] = r[2]; bf[jp * 2 + 1][1] = r[3];
            }
            #pragma unroll
            for (int mi = 0; mi < 2; mi++)
                #pragma unroll
                for (int ni = 0; ni < 8; ni++) {
                    mma16816(acc[mi][ni], ahf[mi], bf[ni]);
                    mma16816(acc[mi][ni], alf[mi], bf[ni]);
                }
            #pragma unroll
            for (int jp = 0; jp < 4; jp++) {
                uint32_t r[4];
                ldsm4(r, b_l + jp * 16 * SBH + ko);
                bf[jp * 2][0] = r[0]; bf[jp * 2][1] = r[1];
                bf[jp * 2 + 1][0] = r[2]; bf[jp * 2 + 1][1] = r[3];
            }
            #pragma unroll
            for (int mi = 0; mi < 2; mi++)
                #pragma unroll
                for (int ni = 0; ni < 8; ni++)
                    mma16816(acc[mi][ni], ahf[mi], bf[ni]);
        }
        __syncthreads();
    }

    // ---- epilogue ----
    const int g = lane >> 2, tg = lane & 3;
    #pragma unroll
    for (int mi = 0; mi < 2; mi++) {
        size_t r0 = m0 + wm * 32 + mi * 16 + g;
        #pragma unroll
        for (int ni = 0; ni < 8; ni++) {
            int col = n0c + wn * 64 + ni * 8 + tg * 2;
            if (col < Hn) {
                float2 v01 = make_float2(acc[mi][ni][0], acc[mi][ni][1]);
                float2 v23 = make_float2(acc[mi][ni][2], acc[mi][ni][3]);
                *(float2*)(out + r0 * Hn + col)       = v01;
                *(float2*)(out + (r0 + 8) * Hn + col) = v23;
            }
        }
    }
}

// ---------------- Phase 2: recurrent scan (Round-3 proven version) -----------
#define KC 220
#define KC4 (KC / 4)
#define WREG 9
#define HBUF 256
#define SCAN_SMEM_BYTES (Hn * KC * 4 + 2 * 4 * HBUF * 4)

__global__ __launch_bounds__(256, 1)
void rnn_scan_kernel(const float* __restrict__ h0,
                     const float* __restrict__ bh,
                     float* out) {
    extern __shared__ float sm[];
    float* WhS = sm;                    // [250][220]
    float* hb  = sm + Hn * KC;          // [2][4][256]

    const int j  = threadIdx.x;
    const int jj = (j < Hn) ? j : (Hn - 1);
    const int b0 = blockIdx.x * 4;

    for (int idx = j; idx < Hn * KC; idx += 256) {
        int r = idx / KC;
        int c = idx - r * KC;
        WhS[idx] = g_WhP[r * 256 + c];
    }
    for (int idx = j; idx < 2 * 4 * HBUF; idx += 256)
        hb[idx] = 0.0f;
    __syncthreads();
    if (j < Hn) {
        #pragma unroll
        for (int bb = 0; bb < 4; bb++)
            hb[bb * HBUF + j] = h0[(size_t)(b0 + bb) * Hn + j];
    }

    const float bias = bh[jj];

    float4 wg[WREG];
    {
        const float4* rowp = (const float4*)(g_WhP + (size_t)jj * 256);
        #pragma unroll
        for (int q = 0; q < WREG; q++)
            wg[q] = rowp[KC4 + q];
    }
    __syncthreads();

    int p = 0;
    for (int t = 0; t < Tn; t++) {
        float xp[4];
        if (j < Hn) {
            #pragma unroll
            for (int bb = 0; bb < 4; bb++)
                xp[bb] = out[((size_t)(b0 + bb) * Tn + t) * Hn + j];
        } else {
            xp[0] = xp[1] = xp[2] = xp[3] = 0.0f;
        }

        float acc[4];
        #pragma unroll
        for (int bb = 0; bb < 4; bb++) acc[bb] = bias;

        const float4* hbp = (const float4*)(hb + p * (4 * HBUF));
        const float4* wrow = (const float4*)(WhS + jj * KC);
        #pragma unroll 5
        for (int kc = 0; kc < KC4; kc++) {
            float4 w = wrow[kc];
            #pragma unroll
            for (int bb = 0; bb < 4; bb++) {
                float4 hv = hbp[bb * 64 + kc];
                acc[bb] += w.x * hv.x;
                acc[bb] += w.y * hv.y;
                acc[bb] += w.z * hv.z;
                acc[bb] += w.w * hv.w;
            }
        }
        #pragma unroll
        for (int q = 0; q < WREG; q++) {
            float4 w = wg[q];
            #pragma unroll
            for (int bb = 0; bb < 4; bb++) {
                float4 hv = hbp[bb * 64 + KC4 + q];
                acc[bb] += w.x * hv.x;
                acc[bb] += w.y * hv.y;
                acc[bb] += w.z * hv.z;
                acc[bb] += w.w * hv.w;
            }
        }

        float* hnx = hb + (1 - p) * (4 * HBUF);
        #pragma unroll
        for (int bb = 0; bb < 4; bb++) {
            float hv = tanhf(acc[bb] + xp[bb]);
            if (j < Hn) {
                hnx[bb * HBUF + j] = hv;
                out[((size_t)(b0 + bb) * Tn + t) * Hn + j] = hv;
            }
        }
        __syncthreads();
        p ^= 1;
    }
}

// ---------------- launch ------------------------------------------------------
extern "C" void kernel_launch(void* const* d_in, const int* in_sizes, int n_in,
                              void* d_out, int out_size) {
    const float* x  = (const float*)d_in[0];   // [512,512,256]
    const float* h0 = (const float*)d_in[1];   // [512,250]
    const float* Wx = (const float*)d_in[2];   // [250,256]
    const float* Wh = (const float*)d_in[3];   // [250,250]
    const float* bh = (const float*)d_in[4];   // [250]
    float* out = (float*)d_out;                // [512,512,250]

    // 1) weight prep
    prep_whp_kernel<<<Hn, 256>>>(Wh);
    prep_wx_kernel<<<256, 256>>>(Wx);

    // 2) xproj HMMA GEMM straight into d_out
    dim3 grid((Bn * Tn) / 128, 2);
    gemm_xproj_hmma<<<grid, 256>>>(x, out);

    // 3) recurrent scan (in-place over d_out)
    cudaFuncSetAttribute(rnn_scan_kernel,
                         cudaFuncAttributeMaxDynamicSharedMemorySize,
                         SCAN_SMEM_BYTES);
    rnn_scan_kernel<<<(Bn / 4), 256, SCAN_SMEM_BYTES>>>(h0, bh, out);
}

// round 8
// speedup vs baseline: 2.0610x; 1.6023x over previous
#include <cuda_runtime.h>
#include <cuda_bf16.h>
#include <math.h>
#include <stdint.h>

// Problem dims
#define Bn 512
#define Tn 512
#define In 256
#define Hn 250

// ---------------- helpers ----------------------------------------------------
__device__ __forceinline__ uint32_t smem_u32(const void* p) {
    uint32_t a;
    asm("{ .reg .u64 t; cvta.to.shared.u64 t, %1; cvt.u32.u64 %0, t; }"
        : "=r"(a) : "l"(p));
    return a;
}
__device__ __forceinline__ uint32_t bf16x2_rn(float lo, float hi) {
    uint32_t r;
    asm("cvt.rn.bf16x2.f32 %0, %1, %2;" : "=r"(r) : "f"(hi), "f"(lo));
    return r;
}
__device__ __forceinline__ void ldsm4(uint32_t* r, uint32_t addr) {
    asm volatile("ldmatrix.sync.aligned.m8n8.x4.shared.b16 {%0,%1,%2,%3}, [%4];"
                 : "=r"(r[0]), "=r"(r[1]), "=r"(r[2]), "=r"(r[3]) : "r"(addr));
}
__device__ __forceinline__ void mma16816(float* c, const uint32_t* a,
                                         const uint32_t* b) {
    asm volatile(
        "mma.sync.aligned.m16n8k16.row.col.f32.bf16.bf16.f32 "
        "{%0,%1,%2,%3}, {%4,%5,%6,%7}, {%8,%9}, {%0,%1,%2,%3};"
        : "+f"(c[0]), "+f"(c[1]), "+f"(c[2]), "+f"(c[3])
        : "r"(a[0]), "r"(a[1]), "r"(a[2]), "r"(a[3]), "r"(b[0]), "r"(b[1]));
}
#define CPASYNC16(dst, src) \
    asm volatile("cp.async.cg.shared.global [%0], [%1], 16;" \
                 :: "r"(dst), "l"(src))
#define CP_COMMIT() asm volatile("cp.async.commit_group;" ::: "memory")
#define CP_WAIT1()  asm volatile("cp.async.wait_group 1;" ::: "memory")

// ---------------- scratch ----------------------------------------------------
__device__ float g_WhP[Hn * 256];                       // Wh padded [250][256]
__device__ unsigned short g_WxH[256 * 256];             // Wx hi bf16 [n][k]
__device__ unsigned short g_WxL[256 * 256];             // Wx lo bf16 [n][k]
__device__ unsigned short g_XH[(size_t)Bn * Tn * In];   // x hi bf16 (128 MB)
__device__ unsigned short g_XL[(size_t)Bn * Tn * In];   // x lo bf16 (128 MB)

__global__ void prep_whp_kernel(const float* __restrict__ Wh) {
    int i = blockIdx.x * blockDim.x + threadIdx.x;
    int r = i >> 8;
    int k = i & 255;
    g_WhP[i] = (k < Hn) ? Wh[r * Hn + k] : 0.0f;
}

__global__ void prep_wx_kernel(const float* __restrict__ Wx) {
    int i = blockIdx.x * blockDim.x + threadIdx.x;   // 256*256
    int r = i >> 8;
    int k = i & 255;
    float w = (r < Hn) ? Wx[r * In + k] : 0.0f;
    uint32_t wb = __float_as_uint(w);
    float hif = __uint_as_float(wb & 0xFFFF0000u);
    g_WxH[i] = (unsigned short)(wb >> 16);
    g_WxL[i] = __bfloat16_as_ushort(__float2bfloat16(w - hif));
}

// split all of x into bf16 hi/lo (memory-bound)
__global__ void prep_x_kernel(const float* __restrict__ X) {
    size_t i = (size_t)blockIdx.x * blockDim.x + threadIdx.x;   // float4 id
    float4 v = ((const float4*)X)[i];
    uint2 hp, lp;
    hp.x = __byte_perm(__float_as_uint(v.x), __float_as_uint(v.y), 0x7632);
    hp.y = __byte_perm(__float_as_uint(v.z), __float_as_uint(v.w), 0x7632);
    #define REM(f) ((f) - __uint_as_float(__float_as_uint(f) & 0xFFFF0000u))
    lp.x = bf16x2_rn(REM(v.x), REM(v.y));
    lp.y = bf16x2_rn(REM(v.z), REM(v.w));
    #undef REM
    ((uint2*)g_XH)[i] = hp;
    ((uint2*)g_XL)[i] = lp;
}

// ---------------- Phase 1: xproj via HMMA bf16-split GEMM (v2) ---------------
// CTA tile 128x128x32-chunk, warp tile 32x64, cp.async double buffer, occ 2.
#define SBH   80                    // smem row stride bytes (32 bf16 + pad)
#define RBUF  (128 * SBH)           // 10240 B per region
#define STG   (4 * RBUF)            // Ah, Al, Bh, Bl per stage = 40960 B
#define SMTOT (2 * STG)             // 81920 B

__global__ __launch_bounds__(256, 2)
void gemm_xproj_hmma(float* __restrict__ out) {
    extern __shared__ __align__(16) char smc[];
    const uint32_t smb = smem_u32(smc);

    const int tid  = threadIdx.x;
    const int lane = tid & 31;
    const int warp = tid >> 5;
    const int wm = warp >> 1;              // 0..3 -> M offset 32*wm
    const int wn = warp & 1;               // 0..1 -> N offset 64*wn
    const size_t m0 = (size_t)blockIdx.x * 128;
    const int n0c = blockIdx.y * 128;

    // per-thread cp.async slots: 2 chunks each for Ah/Al/Bh/Bl
    const int r0 = tid >> 1, c40 = (tid & 1) * 2;      // rows 0..127, c4 {0,2}
    // slot i (i=0,1): row r0, c4 = c40 + i
    const char* gxh = (const char*)g_XH;
    const char* gxl = (const char*)g_XL;
    const char* gwh = (const char*)g_WxH;
    const char* gwl = (const char*)g_WxL;

    float acc[2][8][4];
    #pragma unroll
    for (int mi = 0; mi < 2; mi++)
        #pragma unroll
        for (int ni = 0; ni < 8; ni++)
            #pragma unroll
            for (int q = 0; q < 4; q++) acc[mi][ni][q] = 0.0f;

    // ldmatrix base offsets within a stage (proven R7 geometry)
    const uint32_t aoff = (uint32_t)((wm * 32 + (lane & 15)) * SBH + (lane >> 4) * 16);
    const uint32_t boff = (uint32_t)((wn * 64 + (lane >> 4) * 8 + (lane & 7)) * SBH +
                                     ((lane >> 3) & 1) * 16);

    // ---- stage loader: chunk k0 into stage s ----
    auto load_stage = [&](int s, int k0) {
        uint32_t sb = smb + s * STG;
        #pragma unroll
        for (int i = 0; i < 2; i++) {
            int c4 = c40 + i;
            uint32_t d = sb + r0 * SBH + c4 * 16;
            size_t ao = ((m0 + r0) * In + k0 + c4 * 8) * 2;
            size_t bo = (((size_t)(n0c + r0)) * In + k0 + c4 * 8) * 2;
            CPASYNC16(d,            gxh + ao);
            CPASYNC16(d + RBUF,     gxl + ao);
            CPASYNC16(d + 2 * RBUF, gwh + bo);
            CPASYNC16(d + 3 * RBUF, gwl + bo);
        }
    };

    load_stage(0, 0);  CP_COMMIT();
    load_stage(1, 32); CP_COMMIT();

    for (int c = 0; c < 8; c++) {
        CP_WAIT1();            // chunk c resident (groups 0..c complete)
        __syncthreads();

        const uint32_t sb = smb + (c & 1) * STG;
        const uint32_t a_h = sb + aoff,          a_l = sb + RBUF + aoff;
        const uint32_t b_h = sb + 2 * RBUF + boff, b_l = sb + 3 * RBUF + boff;

        #pragma unroll
        for (int ks = 0; ks < 2; ks++) {
            const uint32_t ko = ks * 32;
            uint32_t ahf[2][4], alf[2][4], bf[8][2];
            ldsm4(ahf[0], a_h + ko);
            ldsm4(ahf[1], a_h + 16 * SBH + ko);
            ldsm4(alf[0], a_l + ko);
            ldsm4(alf[1], a_l + 16 * SBH + ko);
            #pragma unroll
            for (int jp = 0; jp < 4; jp++) {
                uint32_t r[4];
                ldsm4(r, b_h + jp * 16 * SBH + ko);
                bf[jp * 2][0] = r[0]; bf[jp * 2][1] = r[1];
                bf[jp * 2 + 1][0] = r[2]; bf[jp * 2 + 1][1] = r[3];
            }
            #pragma unroll
            for (int mi = 0; mi < 2; mi++)
                #pragma unroll
                for (int ni = 0; ni < 8; ni++) {
                    mma16816(acc[mi][ni], ahf[mi], bf[ni]);
                    mma16816(acc[mi][ni], alf[mi], bf[ni]);
                }
            #pragma unroll
            for (int jp = 0; jp < 4; jp++) {
                uint32_t r[4];
                ldsm4(r, b_l + jp * 16 * SBH + ko);
                bf[jp * 2][0] = r[0]; bf[jp * 2][1] = r[1];
                bf[jp * 2 + 1][0] = r[2]; bf[jp * 2 + 1][1] = r[3];
            }
            #pragma unroll
            for (int mi = 0; mi < 2; mi++)
                #pragma unroll
                for (int ni = 0; ni < 8; ni++)
                    mma16816(acc[mi][ni], ahf[mi], bf[ni]);
        }
        __syncthreads();       // all warps done reading stage c&1

        if (c + 2 < 8) load_stage(c & 1, (c + 2) * 32);
        CP_COMMIT();           // uniform group count (empty group for tail)
    }

    // ---- epilogue ----
    const int g = lane >> 2, tg = lane & 3;
    #pragma unroll
    for (int mi = 0; mi < 2; mi++) {
        size_t r = m0 + wm * 32 + mi * 16 + g;
        #pragma unroll
        for (int ni = 0; ni < 8; ni++) {
            int col = n0c + wn * 64 + ni * 8 + tg * 2;
            if (col < Hn) {
                *(float2*)(out + r * Hn + col) =
                    make_float2(acc[mi][ni][0], acc[mi][ni][1]);
                *(float2*)(out + (r + 8) * Hn + col) =
                    make_float2(acc[mi][ni][2], acc[mi][ni][3]);
            }
        }
    }
}

// ---------------- Phase 2: recurrent scan (Round-3 proven version) -----------
#define KC 220
#define KC4 (KC / 4)
#define WREG 9
#define HBUF 256
#define SCAN_SMEM_BYTES (Hn * KC * 4 + 2 * 4 * HBUF * 4)

__global__ __launch_bounds__(256, 1)
void rnn_scan_kernel(const float* __restrict__ h0,
                     const float* __restrict__ bh,
                     float* out) {
    extern __shared__ float sm[];
    float* WhS = sm;                    // [250][220]
    float* hb  = sm + Hn * KC;          // [2][4][256]

    const int j  = threadIdx.x;
    const int jj = (j < Hn) ? j : (Hn - 1);
    const int b0 = blockIdx.x * 4;

    for (int idx = j; idx < Hn * KC; idx += 256) {
        int r = idx / KC;
        int c = idx - r * KC;
        WhS[idx] = g_WhP[r * 256 + c];
    }
    for (int idx = j; idx < 2 * 4 * HBUF; idx += 256)
        hb[idx] = 0.0f;
    __syncthreads();
    if (j < Hn) {
        #pragma unroll
        for (int bb = 0; bb < 4; bb++)
            hb[bb * HBUF + j] = h0[(size_t)(b0 + bb) * Hn + j];
    }

    const float bias = bh[jj];

    float4 wg[WREG];
    {
        const float4* rowp = (const float4*)(g_WhP + (size_t)jj * 256);
        #pragma unroll
        for (int q = 0; q < WREG; q++)
            wg[q] = rowp[KC4 + q];
    }
    __syncthreads();

    int p = 0;
    for (int t = 0; t < Tn; t++) {
        float xp[4];
        if (j < Hn) {
            #pragma unroll
            for (int bb = 0; bb < 4; bb++)
                xp[bb] = out[((size_t)(b0 + bb) * Tn + t) * Hn + j];
        } else {
            xp[0] = xp[1] = xp[2] = xp[3] = 0.0f;
        }

        float acc[4];
        #pragma unroll
        for (int bb = 0; bb < 4; bb++) acc[bb] = bias;

        const float4* hbp = (const float4*)(hb + p * (4 * HBUF));
        const float4* wrow = (const float4*)(WhS + jj * KC);
        #pragma unroll 5
        for (int kc = 0; kc < KC4; kc++) {
            float4 w = wrow[kc];
            #pragma unroll
            for (int bb = 0; bb < 4; bb++) {
                float4 hv = hbp[bb * 64 + kc];
                acc[bb] += w.x * hv.x;
                acc[bb] += w.y * hv.y;
                acc[bb] += w.z * hv.z;
                acc[bb] += w.w * hv.w;
            }
        }
        #pragma unroll
        for (int q = 0; q < WREG; q++) {
            float4 w = wg[q];
            #pragma unroll
            for (int bb = 0; bb < 4; bb++) {
                float4 hv = hbp[bb * 64 + KC4 + q];
                acc[bb] += w.x * hv.x;
                acc[bb] += w.y * hv.y;
                acc[bb] += w.z * hv.z;
                acc[bb] += w.w * hv.w;
            }
        }

        float* hnx = hb + (1 - p) * (4 * HBUF);
        #pragma unroll
        for (int bb = 0; bb < 4; bb++) {
            float hv = tanhf(acc[bb] + xp[bb]);
            if (j < Hn) {
                hnx[bb * HBUF + j] = hv;
                out[((size_t)(b0 + bb) * Tn + t) * Hn + j] = hv;
            }
        }
        __syncthreads();
        p ^= 1;
    }
}

// ---------------- launch ------------------------------------------------------
extern "C" void kernel_launch(void* const* d_in, const int* in_sizes, int n_in,
                              void* d_out, int out_size) {
    const float* x  = (const float*)d_in[0];   // [512,512,256]
    const float* h0 = (const float*)d_in[1];   // [512,250]
    const float* Wx = (const float*)d_in[2];   // [250,256]
    const float* Wh = (const float*)d_in[3];   // [250,250]
    const float* bh = (const float*)d_in[4];   // [250]
    float* out = (float*)d_out;                // [512,512,250]

    // 1) weight + input prep
    prep_whp_kernel<<<Hn, 256>>>(Wh);
    prep_wx_kernel<<<256, 256>>>(Wx);
    prep_x_kernel<<<((size_t)Bn * Tn * In / 4) / 256, 256>>>(x);

    // 2) xproj HMMA GEMM (double-buffered cp.async, occ 2)
    cudaFuncSetAttribute(gemm_xproj_hmma,
                         cudaFuncAttributeMaxDynamicSharedMemorySize, SMTOT);
    dim3 grid((Bn * Tn) / 128, 2);
    gemm_xproj_hmma<<<grid, 256, SMTOT>>>(out);

    // 3) recurrent scan (in-place over d_out)
    cudaFuncSetAttribute(rnn_scan_kernel,
                         cudaFuncAttributeMaxDynamicSharedMemorySize,
                         SCAN_SMEM_BYTES);
    rnn_scan_kernel<<<(Bn / 4), 256, SCAN_SMEM_BYTES>>>(h0, bh, out);
}